// round 12
// baseline (speedup 1.0000x reference)
#include <cuda_runtime.h>
#include <math.h>

#define NDAG  16384
#define NNODE 48
#define D     62
#define DP    64
#define NCLS  500
#define NPOOL 256   // pool partial blocks
#define APITCH 68   // As row pitch (floats): 16B-aligned rows, conflict-free

typedef unsigned long long ull;

// -------- scratch (static device globals; no runtime allocation) ----------
__device__ float g_atomP[(size_t)NDAG * NNODE * D];  // W_merge[:,62:]@atom + b_merge
__device__ float g_last[(size_t)NDAG * D];           // sink outputs per DAG
__device__ float g_logit[NDAG];                      // last . dag_w
__device__ int   g_maxbits;                          // order-encoded max logit
__device__ float g_part[NPOOL * 64];                 // [c][0..61]=numerator, [62]=sumE
__device__ float g_Wt[64 * 64];                      // W_merge[:,62:]^T, k-major, padded

__device__ __forceinline__ int enc_f(float f) {
    int i = __float_as_int(f);
    return (i >= 0) ? i : (i ^ 0x7FFFFFFF);
}
// packed fp32x2 FMA (Blackwell FFMA2 — only reachable via PTX)
__device__ __forceinline__ void ffma2(ull& d, ull a, ull b) {
    asm("fma.rn.f32x2 %0, %1, %2, %0;" : "+l"(d) : "l"(a), "l"(b));
}
__device__ __forceinline__ ull pack2(float lo, float hi) {
    ull r;
    asm("mov.b64 %0, {%1, %2};" : "=l"(r)
        : "r"(__float_as_uint(lo)), "r"(__float_as_uint(hi)));
    return r;
}
__device__ __forceinline__ float2 unpack2(ull v) {
    unsigned lo, hi;
    asm("mov.b64 {%0, %1}, %2;" : "=r"(lo), "=r"(hi) : "l"(v));
    return make_float2(__uint_as_float(lo), __uint_as_float(hi));
}
__device__ __forceinline__ float ex2a(float x) {   // raw MUFU.EX2
    float r; asm("ex2.approx.ftz.f32 %0, %1;" : "=f"(r) : "f"(x)); return r;
}
#define LOG2E 1.4426950408889634f

// interleaved out layout: k -> float index ((k&31)>>2)*8 + (k>>5)*4 + (k&3)
__device__ __forceinline__ int oidx(int k) {
    return ((k & 31) >> 2) * 8 + (k >> 5) * 4 + (k & 3);
}

// ============================================================================
// padding / reset / prep; launch order keeps k_atomP in capture slot 4
// ============================================================================
__global__ void k_nop() {}
__global__ void k_reset() { if (threadIdx.x == 0) g_maxbits = 0x80000000; }

// one-time transpose: g_Wt[k*64+g] = W_merge[g][62+k], zero-padded to 64x64
__global__ void k_prep(const float* __restrict__ W_merge) {
    int idx = blockIdx.x * 256 + threadIdx.x;   // 4096 total
    int k = idx >> 6, g = idx & 63;
    g_Wt[idx] = (k < D && g < D) ? W_merge[g * (2 * D) + D + k] : 0.f;
}

// ============================================================================
// K1: atomP[node,g] = b_merge[g] + sum_k Wt[k][g] * atoms[node,k]
// Register-tiled outer product: warp w -> outputs [8w,8w+8); lane l -> rows
// {l,l+32,l+64,l+96}. 16 f32x2 accumulators/thread. W loads warp-uniform
// (broadcast), A loads LDS.128 pitch-68 (conflict-free). No reductions.
// ============================================================================
__global__ void __launch_bounds__(256) k_atomP(const float* __restrict__ atoms,
                                               const float* __restrict__ b_merge) {
    extern __shared__ __align__(16) float sm[];
    float* As = sm;                    // 128 x APITCH
    float* Wt = sm + 128 * APITCH;     // 64 x 64 (k-major)
    int tid = threadIdx.x;
    int w = tid >> 5, l = tid & 31;

    // stage Wt (coalesced, conflict-free straight copy)
    for (int m = tid; m < 64 * 64; m += 256) Wt[m] = g_Wt[m];

    // stage atoms coalesced -> pitch-68 rows (256 = 4*62 + 8)
    size_t base = (size_t)blockIdx.x * 128 * D;
    {
        unsigned row = (unsigned)tid / D, col = (unsigned)tid - row * D;
        unsigned idx = tid;
#pragma unroll 1
        for (int j = 0; j < 31; j++) {
            As[row * APITCH + col] = atoms[base + idx];
            idx += 256; row += 4; col += 8;
            if (col >= D) { col -= D; row++; }
        }
    }
    // zero pad cols 62..67 (k-loop runs to 63)
    for (int m = tid; m < 128 * 6; m += 256) {
        int r = m / 6, c = D + m - r * 6;
        As[r * APITCH + c] = 0.f;
    }
    __syncthreads();

    // accumulators init with bias (added once per (row, g))
    ull bb[4];
#pragma unroll
    for (int q = 0; q < 4; q++) {
        int gp = 8 * w + 2 * q;
        float blo = (gp     < D) ? b_merge[gp]     : 0.f;
        float bhi = (gp + 1 < D) ? b_merge[gp + 1] : 0.f;
        bb[q] = pack2(blo, bhi);
    }
    ull acc[16];
#pragma unroll
    for (int r = 0; r < 4; r++)
#pragma unroll
        for (int q = 0; q < 4; q++) acc[r * 4 + q] = bb[q];

    const float* wbase = Wt + 8 * w;          // warp-uniform
    unsigned a0off = l * APITCH;

#pragma unroll 2
    for (int c = 0; c < 16; c++) {            // k = 4c .. 4c+3
        float4 av[4];
        av[0] = *(const float4*)&As[a0off                + 4 * c];
        av[1] = *(const float4*)&As[a0off + 32 * APITCH  + 4 * c];
        av[2] = *(const float4*)&As[a0off + 64 * APITCH  + 4 * c];
        av[3] = *(const float4*)&As[a0off + 96 * APITCH  + 4 * c];
#pragma unroll
        for (int kk = 0; kk < 4; kk++) {
            ulonglong2 wA = *(const ulonglong2*)&wbase[(4 * c + kk) * 64];
            ulonglong2 wB = *(const ulonglong2*)&wbase[(4 * c + kk) * 64 + 4];
#pragma unroll
            for (int r = 0; r < 4; r++) {
                float a = (&av[r].x)[kk];
                ull d = pack2(a, a);
                ffma2(acc[r * 4 + 0], d, wA.x);
                ffma2(acc[r * 4 + 1], d, wA.y);
                ffma2(acc[r * 4 + 2], d, wB.x);
                ffma2(acc[r * 4 + 3], d, wB.y);
            }
        }
    }
    __syncthreads();                           // all A reads done; reuse As

    // store acc -> As (cols 62,63 land in padding, never read back)
#pragma unroll
    for (int r = 0; r < 4; r++) {
        float* dst = &As[(l + 32 * r) * APITCH + 8 * w];
        float2 f0 = unpack2(acc[r * 4 + 0]);
        float2 f1 = unpack2(acc[r * 4 + 1]);
        float2 f2 = unpack2(acc[r * 4 + 2]);
        float2 f3 = unpack2(acc[r * 4 + 3]);
        *(float4*)(dst)     = make_float4(f0.x, f0.y, f1.x, f1.y);
        *(float4*)(dst + 4) = make_float4(f2.x, f2.y, f3.x, f3.y);
    }
    __syncthreads();

    {   // coalesced store
        unsigned row = (unsigned)tid / D, col = (unsigned)tid - row * D;
        unsigned idx = tid;
#pragma unroll 1
        for (int j = 0; j < 31; j++) {
            g_atomP[base + idx] = As[row * APITCH + col];
            idx += 256; row += 4; col += 8;
            if (col >= D) { col -= D; row++; }
        }
    }
}

// ============================================================================
// K2: sequential DAG scan. 1 DAG/CTA; thread (g,h): g=tid>>1, h=tid&1.
// (unchanged — validated)
// ============================================================================
__global__ void __launch_bounds__(128) k_scan(const float* __restrict__ atoms,
                                              const int*   __restrict__ preds,
                                              const float* __restrict__ W_single,
                                              const float* __restrict__ b_single,
                                              const float* __restrict__ W_merge,
                                              const float* __restrict__ att_w,
                                              const float* __restrict__ dag_w) {
    __shared__ float z_sh[(NNODE + 1) * DP];       // +1 sentinel row (zeroed)
    __shared__ __align__(16) float out_sh[DP];     // interleaved layout
    __shared__ float sdot_sh[NNODE + 1];           // pre-scaled by log2e
    __shared__ int4  pred_sh[NNODE];
    __shared__ float red_sh[4];

    int tid = threadIdx.x;
    int g = tid >> 1, h = tid & 1;
    long d = blockIdx.x;

    {   // preds for this DAG: coalesced load + remap (-1 -> 48)
        const int* src = preds + d * NNODE * 4;
        int* dst = (int*)pred_sh;
        for (int i = tid; i < NNODE * 4; i += 128) {
            int v = src[i];
            dst[i] = (v < 0) ? NNODE : v;
        }
    }
    if (tid < DP) z_sh[NNODE * DP + tid] = 0.f;    // sentinel z row
    if (tid == 0) sdot_sh[NNODE] = -1e30f;         // sentinel logit

    // half-row of W_agg (att_w for g==62) packed to match interleaved order
    ull Wr2[16];
    {
        const float* wrow = (g < D)  ? (W_merge + (long)g * (2 * D)) :
                            (g == D) ? att_w : (const float*)0;
#pragma unroll
        for (int jj = 0; jj < 8; jj++) {
#pragma unroll
            for (int q = 0; q < 2; q++) {
                int k0 = h * 32 + 4 * jj + 2 * q;
                float lo = (wrow && k0     < D) ? wrow[k0]     : 0.f;
                float hi = (wrow && k0 + 1 < D) ? wrow[k0 + 1] : 0.f;
                Wr2[2 * jj + q] = pack2(lo, hi);
            }
        }
    }
    float dagw_t = (tid < D) ? dag_w[tid] : 0.f;
    int my_oidx = oidx(g);                         // interleaved store slot
    __syncthreads();

    bool ldmp = (h == 0) && (g < D);
    float mp_next = ldmp ? g_atomP[d * NNODE * D + g] : 0.f;

#pragma unroll 1
    for (int t = 0; t < NNODE; t++) {
        float mp = mp_next;
        if (t + 1 < NNODE && ldmp)
            mp_next = g_atomP[(d * NNODE + t + 1) * D + g];   // prefetch

        int4 pv = pred_sh[t];                                 // CTA-uniform
        float outv = 0.f;
        bool has = (pv.x + pv.y + pv.z + pv.w) != 4 * NNODE;  // any valid
        if (has) {
            float s0 = sdot_sh[pv.x];
            float s1 = sdot_sh[pv.y];
            float s2 = sdot_sh[pv.z];
            float s3 = sdot_sh[pv.w];
            float m = fmaxf(fmaxf(s0, s1), fmaxf(s2, s3));
            float e0 = ex2a(s0 - m);
            float e1 = ex2a(s1 - m);
            float e2 = ex2a(s2 - m);
            float e3 = ex2a(s3 - m);
            float sum = (e0 + e1) + (e2 + e3);
            float e_a = h ? e2 : e0;
            float e_b = h ? e3 : e1;
            int   p_a = h ? pv.z : pv.x;
            int   p_b = h ? pv.w : pv.y;
            float za_h = (g < D) ? (e_a * z_sh[p_a * DP + g]
                                  + e_b * z_sh[p_b * DP + g]) : 0.f;
            float za = za_h + __shfl_xor_sync(0xffffffffu, za_h, 1);
            outv = (g < D) ? fmaxf(mp + __fdividef(za, sum), 0.f) : 0.f;
        } else if (h == 0 && g < D) {
            // rare (t=0 always; t>0 with p~0.0016): relu(W_single@atom + b)
            const float* arow = atoms + (d * NNODE + t) * D;   // bcast, L2-hot
            const float* wrow = W_single + g * D;
            float acc = b_single[g];
#pragma unroll
            for (int k = 0; k < 31; k++) {
                float2 av = *(const float2*)(arow + 2 * k);
                float2 wv = *(const float2*)(wrow + 2 * k);
                acc += wv.x * av.x + wv.y * av.y;
            }
            outv = fmaxf(acc, 0.f);
        }
        if (h == 0) out_sh[my_oidx] = (g < D) ? outv : 0.f;   // interleaved
        __syncthreads();

        {   // half-dot via interleaved reads: lanes' pair hits ONE 128B line
            ull a0 = 0ULL, a1 = 0ULL, a2v = 0ULL, a3 = 0ULL;
            const char* ob = (const char*)out_sh + h * 16;
#pragma unroll
            for (int jj = 0; jj < 8; jj += 2) {
                ulonglong2 oa = *(const ulonglong2*)(ob + 32 * jj);
                ulonglong2 oc = *(const ulonglong2*)(ob + 32 * (jj + 1));
                ffma2(a0,  Wr2[2 * jj],     oa.x);
                ffma2(a1,  Wr2[2 * jj + 1], oa.y);
                ffma2(a2v, Wr2[2 * jj + 2], oc.x);
                ffma2(a3,  Wr2[2 * jj + 3], oc.y);
            }
            float2 f0 = unpack2(a0), f1 = unpack2(a1);
            float2 f2 = unpack2(a2v), f3 = unpack2(a3);
            float part = ((f0.x + f0.y) + (f1.x + f1.y))
                       + ((f2.x + f2.y) + (f3.x + f3.y));
            float tot = part + __shfl_xor_sync(0xffffffffu, part, 1);
            if (h == 0) {
                if (g < D)       z_sh[t * DP + g] = tot;
                else if (g == D) sdot_sh[t] = tot * LOG2E;   // pre-scaled
            }
        }
        if (t == NNODE - 1 && h == 0 && g < D) g_last[d * D + g] = outv;
        __syncthreads();
    }

    // fused logit: L[d] = out_47 . dag_w  (out_sh interleaved)
    float lg = (tid < D) ? out_sh[oidx(tid)] * dagw_t : 0.f;
#pragma unroll
    for (int o = 16; o > 0; o >>= 1) lg += __shfl_xor_sync(0xffffffffu, lg, o);
    if ((tid & 31) == 0) red_sh[tid >> 5] = lg;
    __syncthreads();
    if (tid == 0) {
        float L = (red_sh[0] + red_sh[1]) + (red_sh[2] + red_sh[3]);
        g_logit[d] = L;
        atomicMax(&g_maxbits, enc_f(L));
    }
}

// ============================================================================
// K3: partial softmax-pool. 256 blocks x 64 threads, 64 DAGs per block.
// ============================================================================
__global__ void __launch_bounds__(64) k_pool() {
    __shared__ float e_sh[64];
    int tid = threadIdx.x;
    long base = (long)blockIdx.x * 64;
    int mb = g_maxbits;
    float M = __int_as_float(mb >= 0 ? mb : (mb ^ 0x7FFFFFFF));
    e_sh[tid] = __expf(g_logit[base + tid] - M);
    __syncthreads();
    if (tid < D) {
        float pool = 0.f;
#pragma unroll 4
        for (int i = 0; i < 64; i++)
            pool += e_sh[i] * g_last[(base + i) * D + tid];
        g_part[blockIdx.x * 64 + tid] = pool;
    } else if (tid == D) {
        float sE = 0.f;
#pragma unroll
        for (int i = 0; i < 64; i++) sE += e_sh[i];
        g_part[blockIdx.x * 64 + D] = sE;
    }
}

// ============================================================================
// K4: reduce partials -> pooled; out = sigmoid(W_final @ pooled + b_final)
// ============================================================================
__global__ void __launch_bounds__(512) k_final(const float* __restrict__ W_final,
                                               const float* __restrict__ b_final,
                                               float* __restrict__ out) {
    __shared__ float part[8][64];
    __shared__ float pooled[64];
    int tid = threadIdx.x;
    int c = tid >> 6, col = tid & 63;
    float s = 0.f;
    for (int b = c; b < NPOOL; b += 8) s += g_part[b * 64 + col];
    part[c][col] = s;
    __syncthreads();
    if (tid < 64) {
        float t = 0.f;
#pragma unroll
        for (int i = 0; i < 8; i++) t += part[i][tid];
        pooled[tid] = t;            // pooled[62] = sumE
    }
    __syncthreads();
    float inv = 1.f / pooled[D];
    if (tid < NCLS) {
        float acc = 0.f;
#pragma unroll
        for (int k = 0; k < D; k++) acc += W_final[tid * D + k] * pooled[k];
        acc = b_final[tid] + acc * inv;
        out[tid] = 1.f / (1.f + expf(-acc));
    }
}

// ============================================================================
extern "C" void kernel_launch(void* const* d_in, const int* in_sizes, int n_in,
                              void* d_out, int out_size) {
    const float* atoms    = (const float*)d_in[0];
    const int*   preds    = (const int*)  d_in[1];
    const float* W_single = (const float*)d_in[2];
    const float* b_single = (const float*)d_in[3];
    const float* W_merge  = (const float*)d_in[4];
    const float* b_merge  = (const float*)d_in[5];
    const float* att_w    = (const float*)d_in[6];
    const float* dag_w    = (const float*)d_in[7];
    const float* W_final  = (const float*)d_in[8];
    const float* b_final  = (const float*)d_in[9];
    float* out = (float*)d_out;

    const int smem_atomP = (128 * APITCH + 64 * 64) * sizeof(float);  // 51200
    cudaFuncSetAttribute(k_atomP, cudaFuncAttributeMaxDynamicSharedMemorySize,
                         smem_atomP);

    // capture slot = 4th launch -> k_atomP (verify this round's rewrite)
    k_nop<<<1, 32>>>();
    k_reset<<<1, 32>>>();
    k_prep<<<16, 256>>>(W_merge);
    k_atomP<<<NDAG * NNODE / 128, 256, smem_atomP>>>(atoms, b_merge);
    k_scan<<<NDAG, 128>>>(atoms, preds, W_single, b_single, W_merge, att_w, dag_w);
    k_pool<<<NPOOL, 64>>>();
    k_final<<<1, 512>>>(W_final, b_final, out);
}

// round 13
// speedup vs baseline: 1.2267x; 1.2267x over previous
#include <cuda_runtime.h>
#include <math.h>

#define NDAG  16384
#define NNODE 48
#define D     62
#define DP    64
#define NCLS  500
#define NPOOL 256   // pool partial blocks
#define APITCH 68   // As row pitch (floats): 16B-aligned rows, conflict-free

typedef unsigned long long ull;

// -------- scratch (static device globals; no runtime allocation) ----------
__device__ float g_atomP[(size_t)NDAG * NNODE * D];  // W_merge[:,62:]@atom + b_merge
__device__ float g_last[(size_t)NDAG * D];           // sink outputs per DAG
__device__ float g_logit[NDAG];                      // last . dag_w
__device__ int   g_maxbits;                          // order-encoded max logit
__device__ float g_part[NPOOL * 64];                 // [c][0..61]=numerator, [62]=sumE
__device__ float g_Wt[64 * 64];                      // W_merge[:,62:]^T, k-major, padded

__device__ __forceinline__ int enc_f(float f) {
    int i = __float_as_int(f);
    return (i >= 0) ? i : (i ^ 0x7FFFFFFF);
}
// packed fp32x2 FMA (Blackwell FFMA2 — only reachable via PTX)
__device__ __forceinline__ void ffma2(ull& d, ull a, ull b) {
    asm("fma.rn.f32x2 %0, %1, %2, %0;" : "+l"(d) : "l"(a), "l"(b));
}
__device__ __forceinline__ ull pack2(float lo, float hi) {
    ull r;
    asm("mov.b64 %0, {%1, %2};" : "=l"(r)
        : "r"(__float_as_uint(lo)), "r"(__float_as_uint(hi)));
    return r;
}
__device__ __forceinline__ float2 unpack2(ull v) {
    unsigned lo, hi;
    asm("mov.b64 {%0, %1}, %2;" : "=r"(lo), "=r"(hi) : "l"(v));
    return make_float2(__uint_as_float(lo), __uint_as_float(hi));
}
__device__ __forceinline__ float ex2a(float x) {   // raw MUFU.EX2
    float r; asm("ex2.approx.ftz.f32 %0, %1;" : "=f"(r) : "f"(x)); return r;
}
#define LOG2E 1.4426950408889634f

// interleaved out layout: k -> float index ((k&31)>>2)*8 + (k>>5)*4 + (k&3)
__device__ __forceinline__ int oidx(int k) {
    return ((k & 31) >> 2) * 8 + (k >> 5) * 4 + (k & 3);
}

// ============================================================================
// reset / prep; launch order puts k_scan in the ncu capture slot (4th)
// ============================================================================
__global__ void k_reset() { if (threadIdx.x == 0) g_maxbits = 0x80000000; }

// one-time transpose: g_Wt[k*64+g] = W_merge[g][62+k], zero-padded to 64x64
__global__ void k_prep(const float* __restrict__ W_merge) {
    int idx = blockIdx.x * 256 + threadIdx.x;   // 4096 total
    int k = idx >> 6, g = idx & 63;
    g_Wt[idx] = (k < D && g < D) ? W_merge[g * (2 * D) + D + k] : 0.f;
}

// ============================================================================
// K1: atomP[node,g] = b_merge[g] + sum_k Wt[k][g] * atoms[node,k]
// Register-tiled outer product (validated structure). This round: staging
// loops batched x8 so LDGs issue with MLP~8 instead of one serialized
// round-trip per element (the R12-measured latency bottleneck).
// ============================================================================
__global__ void __launch_bounds__(256) k_atomP(const float* __restrict__ atoms,
                                               const float* __restrict__ b_merge) {
    extern __shared__ __align__(16) float sm[];
    float* As = sm;                    // 128 x APITCH
    float* Wt = sm + 128 * APITCH;     // 64 x 64 (k-major)
    int tid = threadIdx.x;
    int w = tid >> 5, l = tid & 31;

    // stage Wt (coalesced, conflict-free straight copy; 16 indep LDGs)
    for (int m = tid; m < 64 * 64; m += 256) Wt[m] = g_Wt[m];

    // stage atoms coalesced -> pitch-68 rows; batches of 8 for MLP
    size_t base = (size_t)blockIdx.x * 128 * D;
    {
        unsigned row = (unsigned)tid / D, col = (unsigned)tid - ((unsigned)tid / D) * D;
        unsigned ix = tid;
#pragma unroll 1
        for (int b = 0; b < 3; b++) {          // 3 x 8
            float v[8]; unsigned ad[8];
            unsigned r = row, c = col, x = ix;
#pragma unroll
            for (int j = 0; j < 8; j++) {
                v[j] = atoms[base + x];        // independent -> front-batched
                ad[j] = r * APITCH + c;
                x += 256; r += 4; c += 8; if (c >= D) { c -= D; r++; }
            }
#pragma unroll
            for (int j = 0; j < 8; j++) As[ad[j]] = v[j];
            row = r; col = c; ix = x;
        }
        {   // tail 7  (3*8 + 7 = 31; 31*256 = 128*62 exactly)
            float v[7]; unsigned ad[7];
#pragma unroll
            for (int j = 0; j < 7; j++) {
                v[j] = atoms[base + ix];
                ad[j] = row * APITCH + col;
                ix += 256; row += 4; col += 8; if (col >= D) { col -= D; row++; }
            }
#pragma unroll
            for (int j = 0; j < 7; j++) As[ad[j]] = v[j];
        }
    }
    // zero pad cols 62..67 (k-loop runs to 63)
    for (int m = tid; m < 128 * 6; m += 256) {
        int r = m / 6, c = D + m - r * 6;
        As[r * APITCH + c] = 0.f;
    }
    __syncthreads();

    // accumulators init with bias (added once per (row, g))
    ull bb[4];
#pragma unroll
    for (int q = 0; q < 4; q++) {
        int gp = 8 * w + 2 * q;
        float blo = (gp     < D) ? b_merge[gp]     : 0.f;
        float bhi = (gp + 1 < D) ? b_merge[gp + 1] : 0.f;
        bb[q] = pack2(blo, bhi);
    }
    ull acc[16];
#pragma unroll
    for (int r = 0; r < 4; r++)
#pragma unroll
        for (int q = 0; q < 4; q++) acc[r * 4 + q] = bb[q];

    const float* wbase = Wt + 8 * w;          // warp-uniform
    unsigned a0off = l * APITCH;

#pragma unroll 2
    for (int c = 0; c < 16; c++) {            // k = 4c .. 4c+3
        float4 av[4];
        av[0] = *(const float4*)&As[a0off                + 4 * c];
        av[1] = *(const float4*)&As[a0off + 32 * APITCH  + 4 * c];
        av[2] = *(const float4*)&As[a0off + 64 * APITCH  + 4 * c];
        av[3] = *(const float4*)&As[a0off + 96 * APITCH  + 4 * c];
#pragma unroll
        for (int kk = 0; kk < 4; kk++) {
            ulonglong2 wA = *(const ulonglong2*)&wbase[(4 * c + kk) * 64];
            ulonglong2 wB = *(const ulonglong2*)&wbase[(4 * c + kk) * 64 + 4];
#pragma unroll
            for (int r = 0; r < 4; r++) {
                float a = (&av[r].x)[kk];
                ull d = pack2(a, a);
                ffma2(acc[r * 4 + 0], d, wA.x);
                ffma2(acc[r * 4 + 1], d, wA.y);
                ffma2(acc[r * 4 + 2], d, wB.x);
                ffma2(acc[r * 4 + 3], d, wB.y);
            }
        }
    }
    __syncthreads();                           // all A reads done; reuse As

    // store acc -> As (cols 62,63 land in padding, never read back)
#pragma unroll
    for (int r = 0; r < 4; r++) {
        float* dst = &As[(l + 32 * r) * APITCH + 8 * w];
        float2 f0 = unpack2(acc[r * 4 + 0]);
        float2 f1 = unpack2(acc[r * 4 + 1]);
        float2 f2 = unpack2(acc[r * 4 + 2]);
        float2 f3 = unpack2(acc[r * 4 + 3]);
        *(float4*)(dst)     = make_float4(f0.x, f0.y, f1.x, f1.y);
        *(float4*)(dst + 4) = make_float4(f2.x, f2.y, f3.x, f3.y);
    }
    __syncthreads();

    {   // coalesced store, batched x8 (LDS round-trips overlapped)
        unsigned row = (unsigned)tid / D, col = (unsigned)tid - ((unsigned)tid / D) * D;
        unsigned ix = tid;
#pragma unroll 1
        for (int b = 0; b < 3; b++) {
            float v[8]; unsigned gx[8];
            unsigned r = row, c = col, x = ix;
#pragma unroll
            for (int j = 0; j < 8; j++) {
                v[j] = As[r * APITCH + c];
                gx[j] = x;
                x += 256; r += 4; c += 8; if (c >= D) { c -= D; r++; }
            }
#pragma unroll
            for (int j = 0; j < 8; j++) g_atomP[base + gx[j]] = v[j];
            row = r; col = c; ix = x;
        }
        {
            float v[7]; unsigned gx[7];
#pragma unroll
            for (int j = 0; j < 7; j++) {
                v[j] = As[row * APITCH + col];
                gx[j] = ix;
                ix += 256; row += 4; col += 8; if (col >= D) { col -= D; row++; }
            }
#pragma unroll
            for (int j = 0; j < 7; j++) g_atomP[base + gx[j]] = v[j];
        }
    }
}

// ============================================================================
// K2: sequential DAG scan. 1 DAG/CTA; thread (g,h): g=tid>>1, h=tid&1.
// (byte-identical to R11 — being profiled in capture slot 4)
// ============================================================================
__global__ void __launch_bounds__(128) k_scan(const float* __restrict__ atoms,
                                              const int*   __restrict__ preds,
                                              const float* __restrict__ W_single,
                                              const float* __restrict__ b_single,
                                              const float* __restrict__ W_merge,
                                              const float* __restrict__ att_w,
                                              const float* __restrict__ dag_w) {
    __shared__ float z_sh[(NNODE + 1) * DP];       // +1 sentinel row (zeroed)
    __shared__ __align__(16) float out_sh[DP];     // interleaved layout
    __shared__ float sdot_sh[NNODE + 1];           // pre-scaled by log2e
    __shared__ int4  pred_sh[NNODE];
    __shared__ float red_sh[4];

    int tid = threadIdx.x;
    int g = tid >> 1, h = tid & 1;
    long d = blockIdx.x;

    {   // preds for this DAG: coalesced load + remap (-1 -> 48)
        const int* src = preds + d * NNODE * 4;
        int* dst = (int*)pred_sh;
        for (int i = tid; i < NNODE * 4; i += 128) {
            int v = src[i];
            dst[i] = (v < 0) ? NNODE : v;
        }
    }
    if (tid < DP) z_sh[NNODE * DP + tid] = 0.f;    // sentinel z row
    if (tid == 0) sdot_sh[NNODE] = -1e30f;         // sentinel logit

    // half-row of W_agg (att_w for g==62) packed to match interleaved order
    ull Wr2[16];
    {
        const float* wrow = (g < D)  ? (W_merge + (long)g * (2 * D)) :
                            (g == D) ? att_w : (const float*)0;
#pragma unroll
        for (int jj = 0; jj < 8; jj++) {
#pragma unroll
            for (int q = 0; q < 2; q++) {
                int k0 = h * 32 + 4 * jj + 2 * q;
                float lo = (wrow && k0     < D) ? wrow[k0]     : 0.f;
                float hi = (wrow && k0 + 1 < D) ? wrow[k0 + 1] : 0.f;
                Wr2[2 * jj + q] = pack2(lo, hi);
            }
        }
    }
    float dagw_t = (tid < D) ? dag_w[tid] : 0.f;
    int my_oidx = oidx(g);                         // interleaved store slot
    __syncthreads();

    bool ldmp = (h == 0) && (g < D);
    float mp_next = ldmp ? g_atomP[d * NNODE * D + g] : 0.f;

#pragma unroll 1
    for (int t = 0; t < NNODE; t++) {
        float mp = mp_next;
        if (t + 1 < NNODE && ldmp)
            mp_next = g_atomP[(d * NNODE + t + 1) * D + g];   // prefetch

        int4 pv = pred_sh[t];                                 // CTA-uniform
        float outv = 0.f;
        bool has = (pv.x + pv.y + pv.z + pv.w) != 4 * NNODE;  // any valid
        if (has) {
            float s0 = sdot_sh[pv.x];
            float s1 = sdot_sh[pv.y];
            float s2 = sdot_sh[pv.z];
            float s3 = sdot_sh[pv.w];
            float m = fmaxf(fmaxf(s0, s1), fmaxf(s2, s3));
            float e0 = ex2a(s0 - m);
            float e1 = ex2a(s1 - m);
            float e2 = ex2a(s2 - m);
            float e3 = ex2a(s3 - m);
            float sum = (e0 + e1) + (e2 + e3);
            float e_a = h ? e2 : e0;
            float e_b = h ? e3 : e1;
            int   p_a = h ? pv.z : pv.x;
            int   p_b = h ? pv.w : pv.y;
            float za_h = (g < D) ? (e_a * z_sh[p_a * DP + g]
                                  + e_b * z_sh[p_b * DP + g]) : 0.f;
            float za = za_h + __shfl_xor_sync(0xffffffffu, za_h, 1);
            outv = (g < D) ? fmaxf(mp + __fdividef(za, sum), 0.f) : 0.f;
        } else if (h == 0 && g < D) {
            // rare (t=0 always; t>0 with p~0.0016): relu(W_single@atom + b)
            const float* arow = atoms + (d * NNODE + t) * D;   // bcast, L2-hot
            const float* wrow = W_single + g * D;
            float acc = b_single[g];
#pragma unroll
            for (int k = 0; k < 31; k++) {
                float2 av = *(const float2*)(arow + 2 * k);
                float2 wv = *(const float2*)(wrow + 2 * k);
                acc += wv.x * av.x + wv.y * av.y;
            }
            outv = fmaxf(acc, 0.f);
        }
        if (h == 0) out_sh[my_oidx] = (g < D) ? outv : 0.f;   // interleaved
        __syncthreads();

        {   // half-dot via interleaved reads: lanes' pair hits ONE 128B line
            ull a0 = 0ULL, a1 = 0ULL, a2v = 0ULL, a3 = 0ULL;
            const char* ob = (const char*)out_sh + h * 16;
#pragma unroll
            for (int jj = 0; jj < 8; jj += 2) {
                ulonglong2 oa = *(const ulonglong2*)(ob + 32 * jj);
                ulonglong2 oc = *(const ulonglong2*)(ob + 32 * (jj + 1));
                ffma2(a0,  Wr2[2 * jj],     oa.x);
                ffma2(a1,  Wr2[2 * jj + 1], oa.y);
                ffma2(a2v, Wr2[2 * jj + 2], oc.x);
                ffma2(a3,  Wr2[2 * jj + 3], oc.y);
            }
            float2 f0 = unpack2(a0), f1 = unpack2(a1);
            float2 f2 = unpack2(a2v), f3 = unpack2(a3);
            float part = ((f0.x + f0.y) + (f1.x + f1.y))
                       + ((f2.x + f2.y) + (f3.x + f3.y));
            float tot = part + __shfl_xor_sync(0xffffffffu, part, 1);
            if (h == 0) {
                if (g < D)       z_sh[t * DP + g] = tot;
                else if (g == D) sdot_sh[t] = tot * LOG2E;   // pre-scaled
            }
        }
        if (t == NNODE - 1 && h == 0 && g < D) g_last[d * D + g] = outv;
        __syncthreads();
    }

    // fused logit: L[d] = out_47 . dag_w  (out_sh interleaved)
    float lg = (tid < D) ? out_sh[oidx(tid)] * dagw_t : 0.f;
#pragma unroll
    for (int o = 16; o > 0; o >>= 1) lg += __shfl_xor_sync(0xffffffffu, lg, o);
    if ((tid & 31) == 0) red_sh[tid >> 5] = lg;
    __syncthreads();
    if (tid == 0) {
        float L = (red_sh[0] + red_sh[1]) + (red_sh[2] + red_sh[3]);
        g_logit[d] = L;
        atomicMax(&g_maxbits, enc_f(L));
    }
}

// ============================================================================
// K3: partial softmax-pool. 256 blocks x 64 threads, 64 DAGs per block.
// ============================================================================
__global__ void __launch_bounds__(64) k_pool() {
    __shared__ float e_sh[64];
    int tid = threadIdx.x;
    long base = (long)blockIdx.x * 64;
    int mb = g_maxbits;
    float M = __int_as_float(mb >= 0 ? mb : (mb ^ 0x7FFFFFFF));
    e_sh[tid] = __expf(g_logit[base + tid] - M);
    __syncthreads();
    if (tid < D) {
        float pool = 0.f;
#pragma unroll 4
        for (int i = 0; i < 64; i++)
            pool += e_sh[i] * g_last[(base + i) * D + tid];
        g_part[blockIdx.x * 64 + tid] = pool;
    } else if (tid == D) {
        float sE = 0.f;
#pragma unroll
        for (int i = 0; i < 64; i++) sE += e_sh[i];
        g_part[blockIdx.x * 64 + D] = sE;
    }
}

// ============================================================================
// K4: reduce partials -> pooled; out = sigmoid(W_final @ pooled + b_final)
// ============================================================================
__global__ void __launch_bounds__(512) k_final(const float* __restrict__ W_final,
                                               const float* __restrict__ b_final,
                                               float* __restrict__ out) {
    __shared__ float part[8][64];
    __shared__ float pooled[64];
    int tid = threadIdx.x;
    int c = tid >> 6, col = tid & 63;
    float s = 0.f;
    for (int b = c; b < NPOOL; b += 8) s += g_part[b * 64 + col];
    part[c][col] = s;
    __syncthreads();
    if (tid < 64) {
        float t = 0.f;
#pragma unroll
        for (int i = 0; i < 8; i++) t += part[i][tid];
        pooled[tid] = t;            // pooled[62] = sumE
    }
    __syncthreads();
    float inv = 1.f / pooled[D];
    if (tid < NCLS) {
        float acc = 0.f;
#pragma unroll
        for (int k = 0; k < D; k++) acc += W_final[tid * D + k] * pooled[k];
        acc = b_final[tid] + acc * inv;
        out[tid] = 1.f / (1.f + expf(-acc));
    }
}

// ============================================================================
extern "C" void kernel_launch(void* const* d_in, const int* in_sizes, int n_in,
                              void* d_out, int out_size) {
    const float* atoms    = (const float*)d_in[0];
    const int*   preds    = (const int*)  d_in[1];
    const float* W_single = (const float*)d_in[2];
    const float* b_single = (const float*)d_in[3];
    const float* W_merge  = (const float*)d_in[4];
    const float* b_merge  = (const float*)d_in[5];
    const float* att_w    = (const float*)d_in[6];
    const float* dag_w    = (const float*)d_in[7];
    const float* W_final  = (const float*)d_in[8];
    const float* b_final  = (const float*)d_in[9];
    float* out = (float*)d_out;

    const int smem_atomP = (128 * APITCH + 64 * 64) * sizeof(float);  // 51200
    cudaFuncSetAttribute(k_atomP, cudaFuncAttributeMaxDynamicSharedMemorySize,
                         smem_atomP);

    // capture slot = 4th launch -> k_scan this round
    k_reset<<<1, 32>>>();
    k_prep<<<16, 256>>>(W_merge);
    k_atomP<<<NDAG * NNODE / 128, 256, smem_atomP>>>(atoms, b_merge);
    k_scan<<<NDAG, 128>>>(atoms, preds, W_single, b_single, W_merge, att_w, dag_w);
    k_pool<<<NPOOL, 64>>>();
    k_final<<<1, 512>>>(W_final, b_final, out);
}

// round 14
// speedup vs baseline: 1.3209x; 1.0767x over previous
#include <cuda_runtime.h>
#include <math.h>

#define NDAG  16384
#define NNODE 48
#define D     62
#define DP    64
#define NCLS  500
#define NPOOL 256   // pool partial blocks
#define APITCH 68   // As row pitch (floats): 16B-aligned rows, conflict-free

typedef unsigned long long ull;

// -------- scratch (static device globals; no runtime allocation) ----------
__device__ float g_atomP[(size_t)NDAG * NNODE * D];  // W_merge[:,62:]@atom + b_merge
__device__ float g_last[(size_t)NDAG * D];           // sink outputs per DAG
__device__ float g_logit[NDAG];                      // last . dag_w
__device__ int   g_maxbits;                          // order-encoded max logit
__device__ float g_part[NPOOL * 64];                 // [c][0..61]=numerator, [62]=sumE
__device__ float g_Wt[64 * 64];                      // W_merge[:,62:]^T, k-major, padded

__device__ __forceinline__ int enc_f(float f) {
    int i = __float_as_int(f);
    return (i >= 0) ? i : (i ^ 0x7FFFFFFF);
}
// packed fp32x2 FMA (Blackwell FFMA2 — only reachable via PTX)
__device__ __forceinline__ void ffma2(ull& d, ull a, ull b) {
    asm("fma.rn.f32x2 %0, %1, %2, %0;" : "+l"(d) : "l"(a), "l"(b));
}
__device__ __forceinline__ ull pack2(float lo, float hi) {
    ull r;
    asm("mov.b64 %0, {%1, %2};" : "=l"(r)
        : "r"(__float_as_uint(lo)), "r"(__float_as_uint(hi)));
    return r;
}
__device__ __forceinline__ float2 unpack2(ull v) {
    unsigned lo, hi;
    asm("mov.b64 {%0, %1}, %2;" : "=r"(lo), "=r"(hi) : "l"(v));
    return make_float2(__uint_as_float(lo), __uint_as_float(hi));
}
__device__ __forceinline__ float ex2a(float x) {   // raw MUFU.EX2
    float r; asm("ex2.approx.ftz.f32 %0, %1;" : "=f"(r) : "f"(x)); return r;
}
#define LOG2E 1.4426950408889634f

// interleaved out layout: k -> float index ((k&31)>>2)*8 + (k>>5)*4 + (k&3)
__device__ __forceinline__ int oidx(int k) {
    return ((k & 31) >> 2) * 8 + (k >> 5) * 4 + (k & 3);
}

// ============================================================================
// reset / prep; launch order keeps k_scan in the ncu capture slot (4th)
// ============================================================================
__global__ void k_reset() { if (threadIdx.x == 0) g_maxbits = 0x80000000; }

// one-time transpose: g_Wt[k*64+g] = W_merge[g][62+k], zero-padded to 64x64
__global__ void k_prep(const float* __restrict__ W_merge) {
    int idx = blockIdx.x * 256 + threadIdx.x;   // 4096 total
    int k = idx >> 6, g = idx & 63;
    g_Wt[idx] = (k < D && g < D) ? W_merge[g * (2 * D) + D + k] : 0.f;
}

// ============================================================================
// K1: atomP[node,g] = b_merge[g] + sum_k Wt[k][g] * atoms[node,k]
// Register-tiled outer product + MLP-batched staging (validated, unchanged).
// ============================================================================
__global__ void __launch_bounds__(256) k_atomP(const float* __restrict__ atoms,
                                               const float* __restrict__ b_merge) {
    extern __shared__ __align__(16) float sm[];
    float* As = sm;                    // 128 x APITCH
    float* Wt = sm + 128 * APITCH;     // 64 x 64 (k-major)
    int tid = threadIdx.x;
    int w = tid >> 5, l = tid & 31;

    for (int m = tid; m < 64 * 64; m += 256) Wt[m] = g_Wt[m];

    size_t base = (size_t)blockIdx.x * 128 * D;
    {
        unsigned row = (unsigned)tid / D, col = (unsigned)tid - ((unsigned)tid / D) * D;
        unsigned ix = tid;
#pragma unroll 1
        for (int b = 0; b < 3; b++) {          // 3 x 8 batched LDG (MLP~8)
            float v[8]; unsigned ad[8];
            unsigned r = row, c = col, x = ix;
#pragma unroll
            for (int j = 0; j < 8; j++) {
                v[j] = atoms[base + x];
                ad[j] = r * APITCH + c;
                x += 256; r += 4; c += 8; if (c >= D) { c -= D; r++; }
            }
#pragma unroll
            for (int j = 0; j < 8; j++) As[ad[j]] = v[j];
            row = r; col = c; ix = x;
        }
        {   // tail 7
            float v[7]; unsigned ad[7];
#pragma unroll
            for (int j = 0; j < 7; j++) {
                v[j] = atoms[base + ix];
                ad[j] = row * APITCH + col;
                ix += 256; row += 4; col += 8; if (col >= D) { col -= D; row++; }
            }
#pragma unroll
            for (int j = 0; j < 7; j++) As[ad[j]] = v[j];
        }
    }
    for (int m = tid; m < 128 * 6; m += 256) {
        int r = m / 6, c = D + m - r * 6;
        As[r * APITCH + c] = 0.f;
    }
    __syncthreads();

    ull bb[4];
#pragma unroll
    for (int q = 0; q < 4; q++) {
        int gp = 8 * w + 2 * q;
        float blo = (gp     < D) ? b_merge[gp]     : 0.f;
        float bhi = (gp + 1 < D) ? b_merge[gp + 1] : 0.f;
        bb[q] = pack2(blo, bhi);
    }
    ull acc[16];
#pragma unroll
    for (int r = 0; r < 4; r++)
#pragma unroll
        for (int q = 0; q < 4; q++) acc[r * 4 + q] = bb[q];

    const float* wbase = Wt + 8 * w;          // warp-uniform
    unsigned a0off = l * APITCH;

#pragma unroll 2
    for (int c = 0; c < 16; c++) {            // k = 4c .. 4c+3
        float4 av[4];
        av[0] = *(const float4*)&As[a0off                + 4 * c];
        av[1] = *(const float4*)&As[a0off + 32 * APITCH  + 4 * c];
        av[2] = *(const float4*)&As[a0off + 64 * APITCH  + 4 * c];
        av[3] = *(const float4*)&As[a0off + 96 * APITCH  + 4 * c];
#pragma unroll
        for (int kk = 0; kk < 4; kk++) {
            ulonglong2 wA = *(const ulonglong2*)&wbase[(4 * c + kk) * 64];
            ulonglong2 wB = *(const ulonglong2*)&wbase[(4 * c + kk) * 64 + 4];
#pragma unroll
            for (int r = 0; r < 4; r++) {
                float a = (&av[r].x)[kk];
                ull d = pack2(a, a);
                ffma2(acc[r * 4 + 0], d, wA.x);
                ffma2(acc[r * 4 + 1], d, wA.y);
                ffma2(acc[r * 4 + 2], d, wB.x);
                ffma2(acc[r * 4 + 3], d, wB.y);
            }
        }
    }
    __syncthreads();

#pragma unroll
    for (int r = 0; r < 4; r++) {
        float* dst = &As[(l + 32 * r) * APITCH + 8 * w];
        float2 f0 = unpack2(acc[r * 4 + 0]);
        float2 f1 = unpack2(acc[r * 4 + 1]);
        float2 f2 = unpack2(acc[r * 4 + 2]);
        float2 f3 = unpack2(acc[r * 4 + 3]);
        *(float4*)(dst)     = make_float4(f0.x, f0.y, f1.x, f1.y);
        *(float4*)(dst + 4) = make_float4(f2.x, f2.y, f3.x, f3.y);
    }
    __syncthreads();

    {   // coalesced store, batched x8
        unsigned row = (unsigned)tid / D, col = (unsigned)tid - ((unsigned)tid / D) * D;
        unsigned ix = tid;
#pragma unroll 1
        for (int b = 0; b < 3; b++) {
            float v[8]; unsigned gx[8];
            unsigned r = row, c = col, x = ix;
#pragma unroll
            for (int j = 0; j < 8; j++) {
                v[j] = As[r * APITCH + c];
                gx[j] = x;
                x += 256; r += 4; c += 8; if (c >= D) { c -= D; r++; }
            }
#pragma unroll
            for (int j = 0; j < 8; j++) g_atomP[base + gx[j]] = v[j];
            row = r; col = c; ix = x;
        }
        {
            float v[7]; unsigned gx[7];
#pragma unroll
            for (int j = 0; j < 7; j++) {
                v[j] = As[row * APITCH + col];
                gx[j] = ix;
                ix += 256; row += 4; col += 8; if (col >= D) { col -= D; row++; }
            }
#pragma unroll
            for (int j = 0; j < 7; j++) g_atomP[base + gx[j]] = v[j];
        }
    }
}

// ============================================================================
// K2: sequential DAG scan. 1 DAG/CTA; thread (g,h): g=tid>>1, h=tid&1.
// R13 diet: sdot lives in z_sh column 62 (one unified store path); preds
// pre-scaled x64 at staging (gather index = IADD); half-split softmax
// (2 LDS + 2 ex2 per thread, max/sum combined via the existing pair shfl);
// has-test via sentinel magnitude; dag_w load hoisted out of the loop;
// 8 CTAs/SM targeted via launch bounds.
// ============================================================================
__global__ void __launch_bounds__(128, 8) k_scan(const float* __restrict__ atoms,
                                                 const int*   __restrict__ preds,
                                                 const float* __restrict__ W_single,
                                                 const float* __restrict__ b_single,
                                                 const float* __restrict__ W_merge,
                                                 const float* __restrict__ att_w,
                                                 const float* __restrict__ dag_w) {
    __shared__ float z_sh[(NNODE + 1) * DP];       // col 62 = sdot (log2e-scaled)
    __shared__ __align__(16) float out_sh[DP];     // interleaved layout
    __shared__ int   pred_sh[NNODE * 4];           // pre-scaled by 64
    __shared__ float red_sh[4];

    int tid = threadIdx.x;
    int g = tid >> 1, h = tid & 1;
    long d = blockIdx.x;

    {   // preds: coalesced load + remap (-1 -> 48) + pre-scale x64
        const int* src = preds + d * NNODE * 4;
        for (int i = tid; i < NNODE * 4; i += 128) {
            int v = src[i];
            pred_sh[i] = ((v < 0) ? NNODE : v) << 6;
        }
    }
    if (tid < DP)   // sentinel row 48: z = 0, sdot slot = -1e30
        z_sh[NNODE * DP + tid] = (tid == D) ? -1e30f : 0.f;

    // half-row of W_agg (att_w for g==62) packed to match interleaved order
    ull Wr2[16];
    {
        const float* wrow = (g < D)  ? (W_merge + (long)g * (2 * D)) :
                            (g == D) ? att_w : (const float*)0;
#pragma unroll
        for (int jj = 0; jj < 8; jj++) {
#pragma unroll
            for (int q = 0; q < 2; q++) {
                int k0 = h * 32 + 4 * jj + 2 * q;
                float lo = (wrow && k0     < D) ? wrow[k0]     : 0.f;
                float hi = (wrow && k0 + 1 < D) ? wrow[k0 + 1] : 0.f;
                Wr2[2 * jj + q] = pack2(lo, hi);
            }
        }
    }
    int my_oidx = oidx(g);                         // interleaved store slot
    __syncthreads();

    bool ldmp = (h == 0) && (g < D);
    float mp_next = ldmp ? g_atomP[d * NNODE * D + g] : 0.f;

#pragma unroll 1
    for (int t = 0; t < NNODE; t++) {
        float mp = mp_next;
        if (t + 1 < NNODE && ldmp)
            mp_next = g_atomP[(d * NNODE + t + 1) * D + g];   // prefetch

        // this half's 2 preds (already x64): h=0 -> (x,y), h=1 -> (z,w)
        int2 pp = ((const int2*)pred_sh)[2 * t + h];
        float s_a = z_sh[pp.x + D];                // sdot slot (log2e-scaled)
        float s_b = z_sh[pp.y + D];
        float mh = fmaxf(s_a, s_b);
        float m  = fmaxf(mh, __shfl_xor_sync(0xffffffffu, mh, 1));
        float outv = 0.f;
        bool has = m > -1e29f;                     // sentinel = -1e30
        if (has) {
            float e_a = ex2a(s_a - m);
            float e_b = ex2a(s_b - m);
            float sh_ = e_a + e_b;
            float sum = sh_ + __shfl_xor_sync(0xffffffffu, sh_, 1);
            float za_h = (g < D) ? (e_a * z_sh[pp.x + g]
                                  + e_b * z_sh[pp.y + g]) : 0.f;
            float za = za_h + __shfl_xor_sync(0xffffffffu, za_h, 1);
            outv = (g < D) ? fmaxf(mp + __fdividef(za, sum), 0.f) : 0.f;
        } else if (h == 0 && g < D) {
            // rare (t=0 always; t>0 with p~0.0016): relu(W_single@atom + b)
            const float* arow = atoms + (d * NNODE + t) * D;   // bcast, L2-hot
            const float* wrow = W_single + g * D;
            float acc = b_single[g];
#pragma unroll
            for (int k = 0; k < 31; k++) {
                float2 av = *(const float2*)(arow + 2 * k);
                float2 wv = *(const float2*)(wrow + 2 * k);
                acc += wv.x * av.x + wv.y * av.y;
            }
            outv = fmaxf(acc, 0.f);
        }
        if (h == 0) out_sh[my_oidx] = (g < D) ? outv : 0.f;   // interleaved
        __syncthreads();

        {   // half-dot via interleaved reads: pair hits ONE 32B span per load
            ull a0 = 0ULL, a1 = 0ULL, a2v = 0ULL, a3 = 0ULL;
            const char* ob = (const char*)out_sh + h * 16;
#pragma unroll
            for (int jj = 0; jj < 8; jj += 2) {
                ulonglong2 oa = *(const ulonglong2*)(ob + 32 * jj);
                ulonglong2 oc = *(const ulonglong2*)(ob + 32 * (jj + 1));
                ffma2(a0,  Wr2[2 * jj],     oa.x);
                ffma2(a1,  Wr2[2 * jj + 1], oa.y);
                ffma2(a2v, Wr2[2 * jj + 2], oc.x);
                ffma2(a3,  Wr2[2 * jj + 3], oc.y);
            }
            float2 f0 = unpack2(a0), f1 = unpack2(a1);
            float2 f2 = unpack2(a2v), f3 = unpack2(a3);
            float part = ((f0.x + f0.y) + (f1.x + f1.y))
                       + ((f2.x + f2.y) + (f3.x + f3.y));
            float tot = part + __shfl_xor_sync(0xffffffffu, part, 1);
            // unified store: z[t][g] for g<62, sdot (x log2e) at col 62
            if (h == 0 && g <= D)
                z_sh[t * DP + g] = (g == D) ? tot * LOG2E : tot;
        }
        if (t == NNODE - 1 && h == 0 && g < D) g_last[d * D + g] = outv;
        __syncthreads();
    }

    // fused logit: L[d] = out_47 . dag_w  (out_sh interleaved)
    float dagw_t = (tid < D) ? dag_w[tid] : 0.f;   // loaded after mainloop
    float lg = (tid < D) ? out_sh[oidx(tid)] * dagw_t : 0.f;
#pragma unroll
    for (int o = 16; o > 0; o >>= 1) lg += __shfl_xor_sync(0xffffffffu, lg, o);
    if ((tid & 31) == 0) red_sh[tid >> 5] = lg;
    __syncthreads();
    if (tid == 0) {
        float L = (red_sh[0] + red_sh[1]) + (red_sh[2] + red_sh[3]);
        g_logit[d] = L;
        atomicMax(&g_maxbits, enc_f(L));
    }
}

// ============================================================================
// K3: partial softmax-pool. 256 blocks x 64 threads, 64 DAGs per block.
// ============================================================================
__global__ void __launch_bounds__(64) k_pool() {
    __shared__ float e_sh[64];
    int tid = threadIdx.x;
    long base = (long)blockIdx.x * 64;
    int mb = g_maxbits;
    float M = __int_as_float(mb >= 0 ? mb : (mb ^ 0x7FFFFFFF));
    e_sh[tid] = __expf(g_logit[base + tid] - M);
    __syncthreads();
    if (tid < D) {
        float pool = 0.f;
#pragma unroll 4
        for (int i = 0; i < 64; i++)
            pool += e_sh[i] * g_last[(base + i) * D + tid];
        g_part[blockIdx.x * 64 + tid] = pool;
    } else if (tid == D) {
        float sE = 0.f;
#pragma unroll
        for (int i = 0; i < 64; i++) sE += e_sh[i];
        g_part[blockIdx.x * 64 + D] = sE;
    }
}

// ============================================================================
// K4: reduce partials -> pooled; out = sigmoid(W_final @ pooled + b_final)
// ============================================================================
__global__ void __launch_bounds__(512) k_final(const float* __restrict__ W_final,
                                               const float* __restrict__ b_final,
                                               float* __restrict__ out) {
    __shared__ float part[8][64];
    __shared__ float pooled[64];
    int tid = threadIdx.x;
    int c = tid >> 6, col = tid & 63;
    float s = 0.f;
    for (int b = c; b < NPOOL; b += 8) s += g_part[b * 64 + col];
    part[c][col] = s;
    __syncthreads();
    if (tid < 64) {
        float t = 0.f;
#pragma unroll
        for (int i = 0; i < 8; i++) t += part[i][tid];
        pooled[tid] = t;            // pooled[62] = sumE
    }
    __syncthreads();
    float inv = 1.f / pooled[D];
    if (tid < NCLS) {
        float acc = 0.f;
#pragma unroll
        for (int k = 0; k < D; k++) acc += W_final[tid * D + k] * pooled[k];
        acc = b_final[tid] + acc * inv;
        out[tid] = 1.f / (1.f + expf(-acc));
    }
}

// ============================================================================
extern "C" void kernel_launch(void* const* d_in, const int* in_sizes, int n_in,
                              void* d_out, int out_size) {
    const float* atoms    = (const float*)d_in[0];
    const int*   preds    = (const int*)  d_in[1];
    const float* W_single = (const float*)d_in[2];
    const float* b_single = (const float*)d_in[3];
    const float* W_merge  = (const float*)d_in[4];
    const float* b_merge  = (const float*)d_in[5];
    const float* att_w    = (const float*)d_in[6];
    const float* dag_w    = (const float*)d_in[7];
    const float* W_final  = (const float*)d_in[8];
    const float* b_final  = (const float*)d_in[9];
    float* out = (float*)d_out;

    const int smem_atomP = (128 * APITCH + 64 * 64) * sizeof(float);  // 51200
    cudaFuncSetAttribute(k_atomP, cudaFuncAttributeMaxDynamicSharedMemorySize,
                         smem_atomP);

    // capture slot = 4th launch -> k_scan (verify this round's diet)
    k_reset<<<1, 32>>>();
    k_prep<<<16, 256>>>(W_merge);
    k_atomP<<<NDAG * NNODE / 128, 256, smem_atomP>>>(atoms, b_merge);
    k_scan<<<NDAG, 128>>>(atoms, preds, W_single, b_single, W_merge, att_w, dag_w);
    k_pool<<<NPOOL, 64>>>();
    k_final<<<1, 512>>>(W_final, b_final, out);
}